// round 13
// baseline (speedup 1.0000x reference)
#include <cuda_runtime.h>
#include <cuda_fp16.h>

// EdgeDecoder: out[e] = relu(concat(user[i], movie[j]) @ w1^T + b1) @ w2^T + b2
// Restructured:
//   U[i] = user_emb[i]  @ w1[:, :128]^T + b1   (precomputed, fp16 table)
//   M[j] = movie_emb[j] @ w1[:, 128:]^T        (precomputed, fp16 table)
//   out[e] = relu(U[i]+M[j]) . w2 + b2

#define HIDDEN      128
#define MAX_USERS   100000
#define MAX_MOVIES  50000
#define WT_STRIDE   132            // padded row stride for transposed w1 in smem
#define PRE_THREADS 256
#define ROWS_PER_WARP 8
#define SMEM_FLOATS (HIDDEN * WT_STRIDE + 8 * ROWS_PER_WARP * HIDDEN)

__device__ __align__(16) __half g_U[(size_t)MAX_USERS  * HIDDEN];
__device__ __align__(16) __half g_M[(size_t)MAX_MOVIES * HIDDEN];
__device__ int g_idx_is_i64;   // 1 if edge index buffer is int64, 0 if int32
__device__ int g_max_user;     // max referenced user index (exact)
__device__ int g_max_movie;    // max referenced movie index (exact)

__device__ __forceinline__ unsigned long long pack2(float x) {
    unsigned long long r;
    asm("mov.b64 %0, {%1, %1};" : "=l"(r) : "f"(x));
    return r;
}
__device__ __forceinline__ void ffma2(unsigned long long& acc,
                                      unsigned long long w,
                                      unsigned long long x) {
    asm("fma.rn.f32x2 %0, %1, %2, %0;" : "+l"(acc) : "l"(w), "l"(x));
}
__device__ __forceinline__ float2 unpack2(unsigned long long v) {
    float lo, hi;
    asm("mov.b64 {%0, %1}, %2;" : "=f"(lo), "=f"(hi) : "l"(v));
    return make_float2(lo, hi);
}

// ---------------------------------------------------------------------------
// Init+probe: decide int64 vs int32 view of the edge-index buffer, and zero
// the max accumulators.
// ---------------------------------------------------------------------------
__global__ void init_probe_kernel(const int* __restrict__ ei32)
{
    if (threadIdx.x == 0) {
        int all_zero = 1;
        #pragma unroll 8
        for (int k = 1; k < 256; k += 2)
            if (ei32[k] != 0) { all_zero = 0; break; }
        g_idx_is_i64 = all_zero;
        g_max_user   = 0;
        g_max_movie  = 0;
    }
}

// ---------------------------------------------------------------------------
// Exact max-index reduction over both index rows.
// ---------------------------------------------------------------------------
__global__ __launch_bounds__(256)
void reduce_max_kernel(const int* __restrict__ ei32, int E)
{
    __shared__ int s_u[8], s_m[8];
    const int mode64 = g_idx_is_i64;
    int tid  = blockIdx.x * blockDim.x + threadIdx.x;
    int nthr = gridDim.x * blockDim.x;

    int mu = 0, mm = 0;
    for (int e = tid; e < E; e += nthr) {
        int iu, im;
        if (mode64) { iu = ei32[2 * e]; im = ei32[2 * (E + e)]; }
        else        { iu = ei32[e];     im = ei32[E + e]; }
        mu = max(mu, iu);
        mm = max(mm, im);
    }
    #pragma unroll
    for (int o = 16; o > 0; o >>= 1) {
        mu = max(mu, __shfl_xor_sync(0xffffffffu, mu, o));
        mm = max(mm, __shfl_xor_sync(0xffffffffu, mm, o));
    }
    int warp = threadIdx.x >> 5, lane = threadIdx.x & 31;
    if (lane == 0) { s_u[warp] = mu; s_m[warp] = mm; }
    __syncthreads();
    if (threadIdx.x == 0) {
        int bu = s_u[0], bm = s_m[0];
        #pragma unroll
        for (int w = 1; w < 8; w++) { bu = max(bu, s_u[w]); bm = max(bm, s_m[w]); }
        atomicMax(&g_max_user, bu);
        atomicMax(&g_max_movie, bm);
    }
}

// ---------------------------------------------------------------------------
// Precompute kernel (measured-best config: 256 thr, 8 rows/warp, 4-k steps).
// Lane l computes outputs j = 4l..4l+3 via packed f32x2 FMA; results stored
// as fp16 (rounded once at the end).
// ---------------------------------------------------------------------------
__global__ __launch_bounds__(PRE_THREADS, 2)
void precompute_kernel(const float* __restrict__ user_emb,
                       const float* __restrict__ movie_emb,
                       const float* __restrict__ w1,
                       const float* __restrict__ b1,
                       int n_users, int n_movies, int g_user)
{
    extern __shared__ float smem[];
    float* wT = smem;                         // [128][WT_STRIDE]
    float* xs = smem + HIDDEN * WT_STRIDE;    // [8 warps][8 rows][128]

    const float* emb;
    __half*      outT;
    int nrows, addBias, bx, gsz;
    if ((int)blockIdx.x < g_user) {
        emb = user_emb;  outT = g_U;
        nrows = min(n_users, g_max_user + 1);
        addBias = 1;
        bx = blockIdx.x; gsz = g_user;
    } else {
        emb = movie_emb; outT = g_M;
        nrows = min(n_movies, g_max_movie + 1);
        addBias = 0;
        bx = blockIdx.x - g_user; gsz = gridDim.x - g_user;
    }
    int koff = addBias ? 0 : HIDDEN;

    // Stage the relevant 128x128 half of w1, transposed: wT[k][j] = w1[j][koff+k]
    for (int idx = threadIdx.x; idx < HIDDEN * HIDDEN; idx += PRE_THREADS) {
        int j = idx >> 7;               // output index
        int k = idx & (HIDDEN - 1);     // reduction index (coalesced gmem read)
        wT[k * WT_STRIDE + j] = w1[j * (2 * HIDDEN) + koff + k];
    }
    __syncthreads();

    int warp = threadIdx.x >> 5;
    int lane = threadIdx.x & 31;
    float* xw = xs + warp * (ROWS_PER_WARP * HIDDEN);

    float4 bias = make_float4(0.f, 0.f, 0.f, 0.f);
    if (addBias) bias = ((const float4*)b1)[lane];

    int ngroups = (nrows + ROWS_PER_WARP - 1) / ROWS_PER_WARP;
    for (int g = bx * 8 + warp; g < ngroups; g += gsz * 8) {
        int row0 = g * ROWS_PER_WARP;

        // stage 8 input rows (coalesced float4 loads)
        #pragma unroll
        for (int r = 0; r < ROWS_PER_WARP; r++) {
            int row = row0 + r;
            float4 v = make_float4(0.f, 0.f, 0.f, 0.f);
            if (row < nrows)
                v = ((const float4*)(emb + (size_t)row * HIDDEN))[lane];
            ((float4*)(xw + r * HIDDEN))[lane] = v;
        }
        __syncwarp();

        // accumulators: 8 rows x 2 packed pairs (cols 4l..4l+1, 4l+2..4l+3)
        unsigned long long a[ROWS_PER_WARP][2];
        #pragma unroll
        for (int r = 0; r < ROWS_PER_WARP; r++) { a[r][0] = 0ull; a[r][1] = 0ull; }

        const float* wrow = wT + 4 * lane;
        #pragma unroll 2
        for (int kk = 0; kk < HIDDEN; kk += 4) {
            ulonglong2 w[4];
            #pragma unroll
            for (int d = 0; d < 4; d++)
                w[d] = *(const ulonglong2*)(wrow + (kk + d) * WT_STRIDE);
            float4 xv[ROWS_PER_WARP];
            #pragma unroll
            for (int r = 0; r < ROWS_PER_WARP; r++)
                xv[r] = *(const float4*)(xw + r * HIDDEN + kk);

            #pragma unroll
            for (int r = 0; r < ROWS_PER_WARP; r++) {
                unsigned long long xp;
                xp = pack2(xv[r].x);
                ffma2(a[r][0], w[0].x, xp); ffma2(a[r][1], w[0].y, xp);
                xp = pack2(xv[r].y);
                ffma2(a[r][0], w[1].x, xp); ffma2(a[r][1], w[1].y, xp);
                xp = pack2(xv[r].z);
                ffma2(a[r][0], w[2].x, xp); ffma2(a[r][1], w[2].y, xp);
                xp = pack2(xv[r].w);
                ffma2(a[r][0], w[3].x, xp); ffma2(a[r][1], w[3].y, xp);
            }
        }

        #pragma unroll
        for (int r = 0; r < ROWS_PER_WARP; r++) {
            int row = row0 + r;
            if (row < nrows) {
                float2 lo = unpack2(a[r][0]);
                float2 hi = unpack2(a[r][1]);
                __half2 h01 = __floats2half2_rn(lo.x + bias.x, lo.y + bias.y);
                __half2 h23 = __floats2half2_rn(hi.x + bias.z, hi.y + bias.w);
                uint2 st;
                st.x = *(unsigned int*)&h01;
                st.y = *(unsigned int*)&h23;
                ((uint2*)(outT + (size_t)row * HIDDEN))[lane] = st;
            }
        }
        __syncwarp();   // protect xs before next iteration's restage
    }
}

// ---------------------------------------------------------------------------
// Edge kernel: one warp per edge row (256B coalesced fp16 row reads, LDG.64
// per lane), FOUR edges per iteration: 8 row loads in flight, two fused-dual
// shfl reductions. Branch-free index addressing (uniform step/offset),
// single-instruction unsigned clamp. Grid sized to exactly one wave.
// ---------------------------------------------------------------------------
__global__ __launch_bounds__(256)
void edge_kernel(const int* __restrict__ ei32,
                 const float* __restrict__ w2,
                 const float* __restrict__ b2,
                 float* __restrict__ out, int E,
                 int n_users, int n_movies)
{
    int lane = threadIdx.x & 31;
    int warp = (int)((blockIdx.x * blockDim.x + threadIdx.x) >> 5);
    int nw   = (int)((gridDim.x * blockDim.x) >> 5);

    // branch-free index addressing: pos(user e) = e*step, pos(movie e) = moff + e*step
    const int step = g_idx_is_i64 ? 2 : 1;
    const int moff = E * step;
    const unsigned ucl = (unsigned)(n_users - 1);
    const unsigned mcl = (unsigned)(n_movies - 1);

    float4 wv = ((const float4*)w2)[lane];
    float  bb = b2[0];
    const uint2* U2 = (const uint2*)g_U;   // row stride = 32 uint2 (256B)
    const uint2* M2 = (const uint2*)g_M;
    const bool hi_half = (lane & 16) != 0;
    const __half2 z2 = __float2half2_rn(0.f);

    for (int e0 = warp * 4; e0 < E; e0 += nw * 4) {
        int e1 = e0, e2 = e0 + 1, e3 = e0 + 2, e4 = e0 + 3;
        int v2 = e2 < E, v3 = e3 < E, v4 = e4 < E;
        int c2 = v2 ? e2 : e1, c3 = v3 ? e3 : e1, c4 = v4 ? e4 : e1;

        unsigned iu1 = umin((unsigned)ei32[e1 * step], ucl);
        unsigned im1 = umin((unsigned)ei32[moff + e1 * step], mcl);
        unsigned iu2 = umin((unsigned)ei32[c2 * step], ucl);
        unsigned im2 = umin((unsigned)ei32[moff + c2 * step], mcl);
        unsigned iu3 = umin((unsigned)ei32[c3 * step], ucl);
        unsigned im3 = umin((unsigned)ei32[moff + c3 * step], mcl);
        unsigned iu4 = umin((unsigned)ei32[c4 * step], ucl);
        unsigned im4 = umin((unsigned)ei32[moff + c4 * step], mcl);

        // 8 independent 256B coalesced row loads in flight
        uint2 ua = U2[(size_t)iu1 * 32 + lane];
        uint2 ma = M2[(size_t)im1 * 32 + lane];
        uint2 ub = U2[(size_t)iu2 * 32 + lane];
        uint2 mb = M2[(size_t)im2 * 32 + lane];
        uint2 uc = U2[(size_t)iu3 * 32 + lane];
        uint2 mc = M2[(size_t)im3 * 32 + lane];
        uint2 ud = U2[(size_t)iu4 * 32 + lane];
        uint2 md = M2[(size_t)im4 * 32 + lane];

        // h = relu(u+m) in fp16, dot in fp32
        __half2 a01 = __hmax2(__hadd2(*(__half2*)&ua.x, *(__half2*)&ma.x), z2);
        __half2 a23 = __hmax2(__hadd2(*(__half2*)&ua.y, *(__half2*)&ma.y), z2);
        __half2 b01 = __hmax2(__hadd2(*(__half2*)&ub.x, *(__half2*)&mb.x), z2);
        __half2 b23 = __hmax2(__hadd2(*(__half2*)&ub.y, *(__half2*)&mb.y), z2);
        __half2 c01 = __hmax2(__hadd2(*(__half2*)&uc.x, *(__half2*)&mc.x), z2);
        __half2 c23 = __hmax2(__hadd2(*(__half2*)&uc.y, *(__half2*)&mc.y), z2);
        __half2 d01 = __hmax2(__hadd2(*(__half2*)&ud.x, *(__half2*)&md.x), z2);
        __half2 d23 = __hmax2(__hadd2(*(__half2*)&ud.y, *(__half2*)&md.y), z2);

        float2 fa01 = __half22float2(a01), fa23 = __half22float2(a23);
        float2 fb01 = __half22float2(b01), fb23 = __half22float2(b23);
        float2 fc01 = __half22float2(c01), fc23 = __half22float2(c23);
        float2 fd01 = __half22float2(d01), fd23 = __half22float2(d23);

        float s1 = fa01.x * wv.x, s2 = fb01.x * wv.x;
        float s3 = fc01.x * wv.x, s4 = fd01.x * wv.x;
        s1 = fmaf(fa01.y, wv.y, s1); s2 = fmaf(fb01.y, wv.y, s2);
        s3 = fmaf(fc01.y, wv.y, s3); s4 = fmaf(fd01.y, wv.y, s4);
        s1 = fmaf(fa23.x, wv.z, s1); s2 = fmaf(fb23.x, wv.z, s2);
        s3 = fmaf(fc23.x, wv.z, s3); s4 = fmaf(fd23.x, wv.z, s4);
        s1 = fmaf(fa23.y, wv.w, s1); s2 = fmaf(fb23.y, wv.w, s2);
        s3 = fmaf(fc23.y, wv.w, s3); s4 = fmaf(fd23.y, wv.w, s4);

        // two fused dual reductions (edges 1,2) and (edges 3,4), interleaved
        s1 += __shfl_xor_sync(0xffffffffu, s1, 16);
        s2 += __shfl_xor_sync(0xffffffffu, s2, 16);
        s3 += __shfl_xor_sync(0xffffffffu, s3, 16);
        s4 += __shfl_xor_sync(0xffffffffu, s4, 16);
        float tA = hi_half ? s2 : s1;
        float tB = hi_half ? s4 : s3;
        tA += __shfl_xor_sync(0xffffffffu, tA, 8);
        tB += __shfl_xor_sync(0xffffffffu, tB, 8);
        tA += __shfl_xor_sync(0xffffffffu, tA, 4);
        tB += __shfl_xor_sync(0xffffffffu, tB, 4);
        tA += __shfl_xor_sync(0xffffffffu, tA, 2);
        tB += __shfl_xor_sync(0xffffffffu, tB, 2);
        tA += __shfl_xor_sync(0xffffffffu, tA, 1);
        tB += __shfl_xor_sync(0xffffffffu, tB, 1);
        // lane 0: tA=edge1, tB=edge3;  lane 16: tA=edge2, tB=edge4

        if (lane == 0) {
            out[e1] = tA + bb;
            if (v3) out[e3] = tB + bb;
        }
        if (lane == 16) {
            if (v2) out[e2] = tA + bb;
            if (v4) out[e4] = tB + bb;
        }
    }
}

// ---------------------------------------------------------------------------
extern "C" void kernel_launch(void* const* d_in, const int* in_sizes, int n_in,
                              void* d_out, int out_size)
{
    const float* user_emb  = (const float*)d_in[0];
    const float* movie_emb = (const float*)d_in[1];
    const int*   ei32      = (const int*)d_in[2];
    const float* w1        = (const float*)d_in[3];
    const float* b1        = (const float*)d_in[4];
    const float* w2        = (const float*)d_in[5];
    const float* b2        = (const float*)d_in[6];
    float*       out       = (float*)d_out;

    int n_users  = in_sizes[0] / HIDDEN;
    int n_movies = in_sizes[1] / HIDDEN;
    if (n_users  > MAX_USERS)  n_users  = MAX_USERS;
    if (n_movies > MAX_MOVIES) n_movies = MAX_MOVIES;
    int E = out_size;                       // out is [E, 1]

    size_t smem_bytes = (size_t)SMEM_FLOATS * sizeof(float);   // 100352 B
    cudaFuncSetAttribute(precompute_kernel,
                         cudaFuncAttributeMaxDynamicSharedMemorySize,
                         (int)smem_bytes);

    init_probe_kernel<<<1, 32>>>(ei32);
    reduce_max_kernel<<<256, 256>>>(ei32, E);

    // 2 blocks/SM at ~98KB smem, 256 threads: 592 blocks = exactly resident.
    const int g_user = 296, g_movie = 296;
    precompute_kernel<<<g_user + g_movie, PRE_THREADS, smem_bytes>>>(
        user_emb, movie_emb, w1, b1, n_users, n_movies, g_user);

    // 1184 = 148 SMs x 8 blocks of 256 thr -> exactly one wave
    edge_kernel<<<1184, 256>>>(ei32, w2, b2, out, E, n_users, n_movies);
}

// round 14
// speedup vs baseline: 1.1643x; 1.1643x over previous
#include <cuda_runtime.h>
#include <cuda_fp16.h>

// EdgeDecoder: out[e] = relu(concat(user[i], movie[j]) @ w1^T + b1) @ w2^T + b2
// Restructured:
//   U[i] = user_emb[i]  @ w1[:, :128]^T + b1   (precomputed, fp16 table)
//   M[j] = movie_emb[j] @ w1[:, 128:]^T        (precomputed, fp16 table)
//   out[e] = relu(U[i]+M[j]) . w2 + b2

#define HIDDEN      128
#define MAX_USERS   100000
#define MAX_MOVIES  50000
#define WT_STRIDE   132            // padded row stride for transposed w1 in smem
#define PRE_THREADS 256
#define ROWS_PER_WARP 8
#define SMEM_FLOATS (HIDDEN * WT_STRIDE + 8 * ROWS_PER_WARP * HIDDEN)

__device__ __align__(16) __half g_U[(size_t)MAX_USERS  * HIDDEN];
__device__ __align__(16) __half g_M[(size_t)MAX_MOVIES * HIDDEN];
__device__ int g_idx_is_i64;   // 1 if edge index buffer is int64, 0 if int32
__device__ int g_max_user;     // max referenced user index (exact)
__device__ int g_max_movie;    // max referenced movie index (exact)

__device__ __forceinline__ unsigned long long pack2(float x) {
    unsigned long long r;
    asm("mov.b64 %0, {%1, %1};" : "=l"(r) : "f"(x));
    return r;
}
__device__ __forceinline__ void ffma2(unsigned long long& acc,
                                      unsigned long long w,
                                      unsigned long long x) {
    asm("fma.rn.f32x2 %0, %1, %2, %0;" : "+l"(acc) : "l"(w), "l"(x));
}
__device__ __forceinline__ float2 unpack2(unsigned long long v) {
    float lo, hi;
    asm("mov.b64 {%0, %1}, %2;" : "=f"(lo), "=f"(hi) : "l"(v));
    return make_float2(lo, hi);
}

// ---------------------------------------------------------------------------
// Init+probe: warp-parallel dtype probe (ballot over odd int32 words of the
// first 128 int64 slots) + zero the max accumulators.
// ---------------------------------------------------------------------------
__global__ void init_probe_kernel(const int* __restrict__ ei32)
{
    int lane = threadIdx.x & 31;
    int nz = 0;
    #pragma unroll
    for (int k = 0; k < 4; k++) {
        int w = 8 * lane + 2 * k + 1;     // odd words 1..255
        if (ei32[w] != 0) nz = 1;
    }
    unsigned b = __ballot_sync(0xffffffffu, nz);
    if (lane == 0) {
        g_idx_is_i64 = (b == 0);
        g_max_user   = 0;
        g_max_movie  = 0;
    }
}

// ---------------------------------------------------------------------------
// Exact max-index reduction over both index rows. int2 loads keep the
// mode64 path coalesced (8B stride).
// ---------------------------------------------------------------------------
__global__ __launch_bounds__(256)
void reduce_max_kernel(const int* __restrict__ ei32, int E)
{
    __shared__ int s_u[8], s_m[8];
    const int mode64 = g_idx_is_i64;
    int tid  = blockIdx.x * blockDim.x + threadIdx.x;
    int nthr = gridDim.x * blockDim.x;

    int mu = 0, mm = 0;
    if (mode64) {
        const int2* p = (const int2*)ei32;
        for (int e = tid; e < E; e += nthr) {
            mu = max(mu, p[e].x);
            mm = max(mm, p[E + e].x);
        }
    } else {
        for (int e = tid; e < E; e += nthr) {
            mu = max(mu, ei32[e]);
            mm = max(mm, ei32[E + e]);
        }
    }
    #pragma unroll
    for (int o = 16; o > 0; o >>= 1) {
        mu = max(mu, __shfl_xor_sync(0xffffffffu, mu, o));
        mm = max(mm, __shfl_xor_sync(0xffffffffu, mm, o));
    }
    int warp = threadIdx.x >> 5, lane = threadIdx.x & 31;
    if (lane == 0) { s_u[warp] = mu; s_m[warp] = mm; }
    __syncthreads();
    if (threadIdx.x == 0) {
        int bu = s_u[0], bm = s_m[0];
        #pragma unroll
        for (int w = 1; w < 8; w++) { bu = max(bu, s_u[w]); bm = max(bm, s_m[w]); }
        atomicMax(&g_max_user, bu);
        atomicMax(&g_max_movie, bm);
    }
}

// ---------------------------------------------------------------------------
// Precompute kernel (measured-best config: 256 thr, 8 rows/warp, 4-k steps).
// Lane l computes outputs j = 4l..4l+3 via packed f32x2 FMA; results stored
// as fp16 (rounded once at the end).
// ---------------------------------------------------------------------------
__global__ __launch_bounds__(PRE_THREADS, 2)
void precompute_kernel(const float* __restrict__ user_emb,
                       const float* __restrict__ movie_emb,
                       const float* __restrict__ w1,
                       const float* __restrict__ b1,
                       int n_users, int n_movies, int g_user)
{
    extern __shared__ float smem[];
    float* wT = smem;                         // [128][WT_STRIDE]
    float* xs = smem + HIDDEN * WT_STRIDE;    // [8 warps][8 rows][128]

    const float* emb;
    __half*      outT;
    int nrows, addBias, bx, gsz;
    if ((int)blockIdx.x < g_user) {
        emb = user_emb;  outT = g_U;
        nrows = min(n_users, g_max_user + 1);
        addBias = 1;
        bx = blockIdx.x; gsz = g_user;
    } else {
        emb = movie_emb; outT = g_M;
        nrows = min(n_movies, g_max_movie + 1);
        addBias = 0;
        bx = blockIdx.x - g_user; gsz = gridDim.x - g_user;
    }
    int koff = addBias ? 0 : HIDDEN;

    // Stage the relevant 128x128 half of w1, transposed: wT[k][j] = w1[j][koff+k]
    for (int idx = threadIdx.x; idx < HIDDEN * HIDDEN; idx += PRE_THREADS) {
        int j = idx >> 7;               // output index
        int k = idx & (HIDDEN - 1);     // reduction index (coalesced gmem read)
        wT[k * WT_STRIDE + j] = w1[j * (2 * HIDDEN) + koff + k];
    }
    __syncthreads();

    int warp = threadIdx.x >> 5;
    int lane = threadIdx.x & 31;
    float* xw = xs + warp * (ROWS_PER_WARP * HIDDEN);

    float4 bias = make_float4(0.f, 0.f, 0.f, 0.f);
    if (addBias) bias = ((const float4*)b1)[lane];

    int ngroups = (nrows + ROWS_PER_WARP - 1) / ROWS_PER_WARP;
    for (int g = bx * 8 + warp; g < ngroups; g += gsz * 8) {
        int row0 = g * ROWS_PER_WARP;

        // stage 8 input rows (coalesced float4 loads)
        #pragma unroll
        for (int r = 0; r < ROWS_PER_WARP; r++) {
            int row = row0 + r;
            float4 v = make_float4(0.f, 0.f, 0.f, 0.f);
            if (row < nrows)
                v = ((const float4*)(emb + (size_t)row * HIDDEN))[lane];
            ((float4*)(xw + r * HIDDEN))[lane] = v;
        }
        __syncwarp();

        // accumulators: 8 rows x 2 packed pairs (cols 4l..4l+1, 4l+2..4l+3)
        unsigned long long a[ROWS_PER_WARP][2];
        #pragma unroll
        for (int r = 0; r < ROWS_PER_WARP; r++) { a[r][0] = 0ull; a[r][1] = 0ull; }

        const float* wrow = wT + 4 * lane;
        #pragma unroll 2
        for (int kk = 0; kk < HIDDEN; kk += 4) {
            ulonglong2 w[4];
            #pragma unroll
            for (int d = 0; d < 4; d++)
                w[d] = *(const ulonglong2*)(wrow + (kk + d) * WT_STRIDE);
            float4 xv[ROWS_PER_WARP];
            #pragma unroll
            for (int r = 0; r < ROWS_PER_WARP; r++)
                xv[r] = *(const float4*)(xw + r * HIDDEN + kk);

            #pragma unroll
            for (int r = 0; r < ROWS_PER_WARP; r++) {
                unsigned long long xp;
                xp = pack2(xv[r].x);
                ffma2(a[r][0], w[0].x, xp); ffma2(a[r][1], w[0].y, xp);
                xp = pack2(xv[r].y);
                ffma2(a[r][0], w[1].x, xp); ffma2(a[r][1], w[1].y, xp);
                xp = pack2(xv[r].z);
                ffma2(a[r][0], w[2].x, xp); ffma2(a[r][1], w[2].y, xp);
                xp = pack2(xv[r].w);
                ffma2(a[r][0], w[3].x, xp); ffma2(a[r][1], w[3].y, xp);
            }
        }

        #pragma unroll
        for (int r = 0; r < ROWS_PER_WARP; r++) {
            int row = row0 + r;
            if (row < nrows) {
                float2 lo = unpack2(a[r][0]);
                float2 hi = unpack2(a[r][1]);
                __half2 h01 = __floats2half2_rn(lo.x + bias.x, lo.y + bias.y);
                __half2 h23 = __floats2half2_rn(hi.x + bias.z, hi.y + bias.w);
                uint2 st;
                st.x = *(unsigned int*)&h01;
                st.y = *(unsigned int*)&h23;
                ((uint2*)(outT + (size_t)row * HIDDEN))[lane] = st;
            }
        }
        __syncwarp();   // protect xs before next iteration's restage
    }
}

// ---------------------------------------------------------------------------
// Edge kernel: one warp per edge row (256B coalesced fp16 row reads), FOUR
// edges per iteration (8 row loads in flight), grid 2048 (multi-wave for
// rebalancing). Vectorized uint4 index loads on the aligned fast path,
// scalar clamped tail otherwise. Two fused-dual shfl reductions.
// ---------------------------------------------------------------------------
__global__ __launch_bounds__(256)
void edge_kernel(const int* __restrict__ ei32,
                 const float* __restrict__ w2,
                 const float* __restrict__ b2,
                 float* __restrict__ out, int E,
                 int n_users, int n_movies)
{
    int lane = threadIdx.x & 31;
    int warp = (int)((blockIdx.x * blockDim.x + threadIdx.x) >> 5);
    int nw   = (int)((gridDim.x * blockDim.x) >> 5);

    const int mode64 = g_idx_is_i64;
    const int step = mode64 ? 2 : 1;
    const int moff = E * step;
    const unsigned ucl = (unsigned)(n_users - 1);
    const unsigned mcl = (unsigned)(n_movies - 1);
    // vector idx loads need the movie-row base 16B-aligned
    const bool vec_ok = mode64 ? ((E & 1) == 0) : ((E & 3) == 0);

    float4 wv = ((const float4*)w2)[lane];
    float  bb = b2[0];
    const uint2* U2 = (const uint2*)g_U;   // row stride = 32 uint2 (256B)
    const uint2* M2 = (const uint2*)g_M;
    const bool hi_half = (lane & 16) != 0;
    const __half2 z2 = __float2half2_rn(0.f);

    for (int e0 = warp * 4; e0 < E; e0 += nw * 4) {
        unsigned iu[4], im[4];
        bool full = (e0 + 3 < E);

        if (full && vec_ok) {
            if (!mode64) {
                uint4 ru = *(const uint4*)(ei32 + e0);
                uint4 rm = *(const uint4*)(ei32 + E + e0);
                iu[0] = ru.x; iu[1] = ru.y; iu[2] = ru.z; iu[3] = ru.w;
                im[0] = rm.x; im[1] = rm.y; im[2] = rm.z; im[3] = rm.w;
            } else {
                const uint4* pu = (const uint4*)(ei32 + 2 * e0);
                uint4 a = pu[0], b = pu[1];
                iu[0] = a.x; iu[1] = a.z; iu[2] = b.x; iu[3] = b.z;
                const uint4* pm = (const uint4*)(ei32 + 2 * E + 2 * e0);
                uint4 c = pm[0], d = pm[1];
                im[0] = c.x; im[1] = c.z; im[2] = d.x; im[3] = d.z;
            }
        } else {
            #pragma unroll
            for (int i = 0; i < 4; i++) {
                int ec = min(e0 + i, E - 1);
                iu[i] = (unsigned)ei32[ec * step];
                im[i] = (unsigned)ei32[moff + ec * step];
            }
        }
        #pragma unroll
        for (int i = 0; i < 4; i++) {
            iu[i] = umin(iu[i], ucl);
            im[i] = umin(im[i], mcl);
        }

        // 8 independent 256B coalesced row loads in flight
        uint2 u[4], m[4];
        #pragma unroll
        for (int i = 0; i < 4; i++) {
            u[i] = U2[(size_t)iu[i] * 32 + lane];
            m[i] = M2[(size_t)im[i] * 32 + lane];
        }

        // h = relu(u+m) in fp16, dot in fp32
        float s[4];
        #pragma unroll
        for (int i = 0; i < 4; i++) {
            __half2 h01 = __hmax2(__hadd2(*(__half2*)&u[i].x, *(__half2*)&m[i].x), z2);
            __half2 h23 = __hmax2(__hadd2(*(__half2*)&u[i].y, *(__half2*)&m[i].y), z2);
            float2 f01 = __half22float2(h01);
            float2 f23 = __half22float2(h23);
            float t = f01.x * wv.x;
            t = fmaf(f01.y, wv.y, t);
            t = fmaf(f23.x, wv.z, t);
            t = fmaf(f23.y, wv.w, t);
            s[i] = t;
        }

        // two fused dual reductions (edges 0,1) and (edges 2,3), interleaved
        #pragma unroll
        for (int i = 0; i < 4; i++)
            s[i] += __shfl_xor_sync(0xffffffffu, s[i], 16);
        float tA = hi_half ? s[1] : s[0];
        float tB = hi_half ? s[3] : s[2];
        tA += __shfl_xor_sync(0xffffffffu, tA, 8);
        tB += __shfl_xor_sync(0xffffffffu, tB, 8);
        tA += __shfl_xor_sync(0xffffffffu, tA, 4);
        tB += __shfl_xor_sync(0xffffffffu, tB, 4);
        tA += __shfl_xor_sync(0xffffffffu, tA, 2);
        tB += __shfl_xor_sync(0xffffffffu, tB, 2);
        tA += __shfl_xor_sync(0xffffffffu, tA, 1);
        tB += __shfl_xor_sync(0xffffffffu, tB, 1);
        // lane 0: tA=edge0, tB=edge2;  lane 16: tA=edge1, tB=edge3

        if (lane == 0) {
            out[e0] = tA + bb;
            if (e0 + 2 < E) out[e0 + 2] = tB + bb;
        }
        if (lane == 16) {
            if (e0 + 1 < E) out[e0 + 1] = tA + bb;
            if (e0 + 3 < E) out[e0 + 3] = tB + bb;
        }
    }
}

// ---------------------------------------------------------------------------
extern "C" void kernel_launch(void* const* d_in, const int* in_sizes, int n_in,
                              void* d_out, int out_size)
{
    const float* user_emb  = (const float*)d_in[0];
    const float* movie_emb = (const float*)d_in[1];
    const int*   ei32      = (const int*)d_in[2];
    const float* w1        = (const float*)d_in[3];
    const float* b1        = (const float*)d_in[4];
    const float* w2        = (const float*)d_in[5];
    const float* b2        = (const float*)d_in[6];
    float*       out       = (float*)d_out;

    int n_users  = in_sizes[0] / HIDDEN;
    int n_movies = in_sizes[1] / HIDDEN;
    if (n_users  > MAX_USERS)  n_users  = MAX_USERS;
    if (n_movies > MAX_MOVIES) n_movies = MAX_MOVIES;
    int E = out_size;                       // out is [E, 1]

    size_t smem_bytes = (size_t)SMEM_FLOATS * sizeof(float);   // 100352 B
    cudaFuncSetAttribute(precompute_kernel,
                         cudaFuncAttributeMaxDynamicSharedMemorySize,
                         (int)smem_bytes);

    init_probe_kernel<<<1, 32>>>(ei32);
    reduce_max_kernel<<<1184, 256>>>(ei32, E);

    // 2 blocks/SM at ~98KB smem, 256 threads: 592 blocks = exactly resident.
    const int g_user = 296, g_movie = 296;
    precompute_kernel<<<g_user + g_movie, PRE_THREADS, smem_bytes>>>(
        user_emb, movie_emb, w1, b1, n_users, n_movies, g_user);

    edge_kernel<<<2048, 256>>>(ei32, w2, b2, out, E, n_users, n_movies);
}

// round 15
// speedup vs baseline: 1.2200x; 1.0478x over previous
#include <cuda_runtime.h>
#include <cuda_fp16.h>
#include <cstdint>

// EdgeDecoder: out[e] = relu(concat(user[i], movie[j]) @ w1^T + b1) @ w2^T + b2
//   U[i] = user_emb[i]  @ w1[:, :128]^T + b1   (mma.sync tf32 2x-split, fp16 table)
//   M[j] = movie_emb[j] @ w1[:, 128:]^T
//   out[e] = relu(U[i]+M[j]) . w2 + b2

#define HIDDEN      128
#define MAX_USERS   100000
#define MAX_MOVIES  50000
#define A_STRIDE    132   // padded fp32 row stride for A tile in smem

__device__ __align__(16) __half g_U[(size_t)MAX_USERS  * HIDDEN];
__device__ __align__(16) __half g_M[(size_t)MAX_MOVIES * HIDDEN];
__device__ int g_idx_is_i64;   // 1 if edge index buffer is int64, 0 if int32
__device__ int g_max_user;     // max referenced user index (exact)
__device__ int g_max_movie;    // max referenced movie index (exact)

__device__ __forceinline__ uint32_t f2tf32(float x) {
    uint32_t r;
    asm("cvt.rna.tf32.f32 %0, %1;" : "=r"(r) : "f"(x));
    return r;
}
__device__ __forceinline__ void mma8(float4& d,
                                     uint32_t a0, uint32_t a1, uint32_t a2, uint32_t a3,
                                     uint32_t b0, uint32_t b1) {
    asm volatile(
        "mma.sync.aligned.m16n8k8.row.col.f32.tf32.tf32.f32 "
        "{%0,%1,%2,%3},{%4,%5,%6,%7},{%8,%9},{%0,%1,%2,%3};"
        : "+f"(d.x), "+f"(d.y), "+f"(d.z), "+f"(d.w)
        : "r"(a0), "r"(a1), "r"(a2), "r"(a3), "r"(b0), "r"(b1));
}

// ---------------------------------------------------------------------------
// Init+probe: warp-parallel dtype probe + zero max accumulators.
// ---------------------------------------------------------------------------
__global__ void init_probe_kernel(const int* __restrict__ ei32)
{
    int lane = threadIdx.x & 31;
    int nz = 0;
    #pragma unroll
    for (int k = 0; k < 4; k++) {
        int w = 8 * lane + 2 * k + 1;     // odd words 1..255
        if (ei32[w] != 0) nz = 1;
    }
    unsigned b = __ballot_sync(0xffffffffu, nz);
    if (lane == 0) {
        g_idx_is_i64 = (b == 0);
        g_max_user   = 0;
        g_max_movie  = 0;
    }
}

// ---------------------------------------------------------------------------
// Exact max-index reduction over both index rows.
// ---------------------------------------------------------------------------
__global__ __launch_bounds__(256)
void reduce_max_kernel(const int* __restrict__ ei32, int E)
{
    __shared__ int s_u[8], s_m[8];
    const int mode64 = g_idx_is_i64;
    int tid  = blockIdx.x * blockDim.x + threadIdx.x;
    int nthr = gridDim.x * blockDim.x;

    int mu = 0, mm = 0;
    if (mode64) {
        const int2* p = (const int2*)ei32;
        for (int e = tid; e < E; e += nthr) {
            mu = max(mu, p[e].x);
            mm = max(mm, p[E + e].x);
        }
    } else {
        for (int e = tid; e < E; e += nthr) {
            mu = max(mu, ei32[e]);
            mm = max(mm, ei32[E + e]);
        }
    }
    #pragma unroll
    for (int o = 16; o > 0; o >>= 1) {
        mu = max(mu, __shfl_xor_sync(0xffffffffu, mu, o));
        mm = max(mm, __shfl_xor_sync(0xffffffffu, mm, o));
    }
    int warp = threadIdx.x >> 5, lane = threadIdx.x & 31;
    if (lane == 0) { s_u[warp] = mu; s_m[warp] = mm; }
    __syncthreads();
    if (threadIdx.x == 0) {
        int bu = s_u[0], bm = s_m[0];
        #pragma unroll
        for (int w = 1; w < 8; w++) { bu = max(bu, s_u[w]); bm = max(bm, s_m[w]); }
        atomicMax(&g_max_user, bu);
        atomicMax(&g_max_movie, bm);
    }
}

// ---------------------------------------------------------------------------
// Tensor-core precompute via mma.sync m16n8k8 tf32 with exact 2-term split:
//   D = Ahi*Bhi + Alo*Bhi + Ahi*Blo   (lo*lo dropped, ~2^-24 rel)
// Blocks [0, g_user) build U (+b1), the rest build M.
// B (weight half) is staged ONCE per CTA, pre-arranged in fragment layout:
//   Bs[kk][nb][lane] = float4(bhi0, bhi1, blo0, blo1)  -> one LDS.128/frag.
// A tiles (128 rows) staged row-major (stride 132, conflict-free frag LDS).
// Each warp computes a 16x128 output slice; epilogue converts to fp16.
// ---------------------------------------------------------------------------
#define SM_B_FLOATS  (16 * 16 * 32 * 4)   // 8192 float4 = 131072 B
#define SM_PRE_FLOATS (128 * A_STRIDE + SM_B_FLOATS + 128)

__global__ __launch_bounds__(256, 1)
void precompute_mma(const float* __restrict__ user_emb,
                    const float* __restrict__ movie_emb,
                    const float* __restrict__ w1,
                    const float* __restrict__ b1,
                    int n_users, int n_movies, int g_user)
{
    extern __shared__ float sm[];
    float* As = sm;                          // [128][A_STRIDE]
    float* Bs = sm + 128 * A_STRIDE;         // [16kk][16nb][32lane] float4
    float* bs = Bs + SM_B_FLOATS;            // [128] bias

    const float* emb;
    __half*      outT;
    int nrows, addBias, cta, ncta;
    if ((int)blockIdx.x < g_user) {
        emb = user_emb;  outT = g_U;
        nrows = min(n_users, g_max_user + 1);
        addBias = 1; cta = blockIdx.x; ncta = g_user;
    } else {
        emb = movie_emb; outT = g_M;
        nrows = min(n_movies, g_max_movie + 1);
        addBias = 0; cta = blockIdx.x - g_user; ncta = gridDim.x - g_user;
    }
    int koff = addBias ? 0 : HIDDEN;
    int tid = threadIdx.x;

    // Stage B fragments (hi+lo) and bias.
    // Fragment map (PTX ISA m16n8k8.tf32, B col-major k8xn8):
    //   b0 = B[k = lane%4][n = lane/4], b1 = B[k = lane%4 + 4][n = lane/4]
    // with B[k][n] = w1[n][koff + k].
    for (int idx = tid; idx < 16 * 16 * 32; idx += 256) {
        int t  = idx & 31;
        int nb = (idx >> 5) & 15;
        int kk = idx >> 9;
        int k = kk * 8 + (t & 3);
        int n = nb * 8 + (t >> 2);
        float w0 = w1[n * (2 * HIDDEN) + koff + k];
        float w4 = w1[n * (2 * HIDDEN) + koff + k + 4];
        uint32_t h0 = f2tf32(w0), h1 = f2tf32(w4);
        uint32_t l0 = f2tf32(w0 - __uint_as_float(h0));
        uint32_t l1 = f2tf32(w4 - __uint_as_float(h1));
        float4 pk;
        pk.x = __uint_as_float(h0); pk.y = __uint_as_float(h1);
        pk.z = __uint_as_float(l0); pk.w = __uint_as_float(l1);
        ((float4*)Bs)[idx] = pk;
    }
    if (tid < 128) bs[tid] = addBias ? b1[tid] : 0.f;
    __syncthreads();

    int warp = tid >> 5, lane = tid & 31;
    int r = lane >> 2, q = lane & 3;
    int ntiles = (nrows + 127) >> 7;

    for (int tile = cta; tile < ntiles; tile += ncta) {
        int row0 = tile << 7;

        // stage A tile: 128 rows x 128 floats (coalesced float4)
        for (int i = tid; i < 128 * 32; i += 256) {
            int rr = i >> 5, c4 = i & 31;
            int grow = min(row0 + rr, nrows - 1);
            float4 v = ((const float4*)(emb + (size_t)grow * HIDDEN))[c4];
            *(float4*)(As + rr * A_STRIDE + c4 * 4) = v;
        }
        __syncthreads();

        const float* Aw = As + (warp * 16) * A_STRIDE;
        float4 acc[16];
        #pragma unroll
        for (int nb = 0; nb < 16; nb++) acc[nb] = make_float4(0.f, 0.f, 0.f, 0.f);

        #pragma unroll 2
        for (int kk = 0; kk < 16; kk++) {
            // A fragment (row-major m16xk8): a0=[r][q] a1=[r+8][q] a2=[r][q+4] a3=[r+8][q+4]
            float af0 = Aw[r * A_STRIDE + kk * 8 + q];
            float af1 = Aw[(r + 8) * A_STRIDE + kk * 8 + q];
            float af2 = Aw[r * A_STRIDE + kk * 8 + q + 4];
            float af3 = Aw[(r + 8) * A_STRIDE + kk * 8 + q + 4];
            uint32_t ah0 = f2tf32(af0), ah1 = f2tf32(af1);
            uint32_t ah2 = f2tf32(af2), ah3 = f2tf32(af3);
            uint32_t al0 = f2tf32(af0 - __uint_as_float(ah0));
            uint32_t al1 = f2tf32(af1 - __uint_as_float(ah1));
            uint32_t al2 = f2tf32(af2 - __uint_as_float(ah2));
            uint32_t al3 = f2tf32(af3 - __uint_as_float(ah3));

            const float4* Bk = (const float4*)Bs + kk * 512 + lane;
            #pragma unroll
            for (int nb = 0; nb < 16; nb++) {
                float4 bp = Bk[nb * 32];
                uint32_t bh0 = __float_as_uint(bp.x), bh1 = __float_as_uint(bp.y);
                uint32_t bl0 = __float_as_uint(bp.z), bl1 = __float_as_uint(bp.w);
                mma8(acc[nb], ah0, ah1, ah2, ah3, bh0, bh1);
                mma8(acc[nb], al0, al1, al2, al3, bh0, bh1);
                mma8(acc[nb], ah0, ah1, ah2, ah3, bl0, bl1);
            }
        }

        // Epilogue: D frag rows r, r+8; cols nb*8 + q*2 (+1). fp16 store.
        int grow0 = row0 + warp * 16 + r;
        int grow1 = grow0 + 8;
        bool v0 = grow0 < nrows, v1 = grow1 < nrows;
        #pragma unroll
        for (int nb = 0; nb < 16; nb++) {
            int c = nb * 8 + q * 2;
            float2 bb = *(float2*)(bs + c);
            __half2 p0 = __floats2half2_rn(acc[nb].x + bb.x, acc[nb].y + bb.y);
            __half2 p1 = __floats2half2_rn(acc[nb].z + bb.x, acc[nb].w + bb.y);
            if (v0) *(__half2*)(outT + (size_t)grow0 * HIDDEN + c) = p0;
            if (v1) *(__half2*)(outT + (size_t)grow1 * HIDDEN + c) = p1;
        }
        __syncthreads();   // A smem reuse next tile
    }
}

// ---------------------------------------------------------------------------
// Edge kernel (R14 measured-best, 57.4us): warp per row, 4 edges/iter,
// vectorized index loads, two fused-dual shfl reductions, grid 2048.
// ---------------------------------------------------------------------------
__global__ __launch_bounds__(256)
void edge_kernel(const int* __restrict__ ei32,
                 const float* __restrict__ w2,
                 const float* __restrict__ b2,
                 float* __restrict__ out, int E,
                 int n_users, int n_movies)
{
    int lane = threadIdx.x & 31;
    int warp = (int)((blockIdx.x * blockDim.x + threadIdx.x) >> 5);
    int nw   = (int)((gridDim.x * blockDim.x) >> 5);

    const int mode64 = g_idx_is_i64;
    const int step = mode64 ? 2 : 1;
    const int moff = E * step;
    const unsigned ucl = (unsigned)(n_users - 1);
    const unsigned mcl = (unsigned)(n_movies - 1);
    const bool vec_ok = mode64 ? ((E & 1) == 0) : ((E & 3) == 0);

    float4 wv = ((const float4*)w2)[lane];
    float  bb = b2[0];
    const uint2* U2 = (const uint2*)g_U;   // row stride = 32 uint2 (256B)
    const uint2* M2 = (const uint2*)g_M;
    const bool hi_half = (lane & 16) != 0;
    const __half2 z2 = __float2half2_rn(0.f);

    for (int e0 = warp * 4; e0 < E; e0 += nw * 4) {
        unsigned iu[4], im[4];
        bool full = (e0 + 3 < E);

        if (full && vec_ok) {
            if (!mode64) {
                uint4 ru = *(const uint4*)(ei32 + e0);
                uint4 rm = *(const uint4*)(ei32 + E + e0);
                iu[0] = ru.x; iu[1] = ru.y; iu[2] = ru.z; iu[3] = ru.w;
                im[0] = rm.x; im[1] = rm.y; im[2] = rm.z; im[3] = rm.w;
            } else {
                const uint4* pu = (const uint4*)(ei32 + 2 * e0);
                uint4 a = pu[0], b = pu[1];
                iu[0] = a.x; iu[1] = a.z; iu[2] = b.x; iu[3] = b.z;
                const uint4* pm = (const uint4*)(ei32 + 2 * E + 2 * e0);
                uint4 c = pm[0], d = pm[1];
                im[0] = c.x; im[1] = c.z; im[2] = d.x; im[3] = d.z;
            }
        } else {
            #pragma unroll
            for (int i = 0; i < 4; i++) {
                int ec = min(e0 + i, E - 1);
                iu[i] = (unsigned)ei32[ec * step];
                im[i] = (unsigned)ei32[moff + ec * step];
            }
        }
        #pragma unroll
        for (int i = 0; i < 4; i++) {
            iu[i] = umin(iu[i], ucl);
            im[i] = umin(im[i], mcl);
        }

        uint2 u[4], m[4];
        #pragma unroll
        for (int i = 0; i < 4; i++) {
            u[i] = U2[(size_t)iu[i] * 32 + lane];
            m[i] = M2[(size_t)im[i] * 32 + lane];
        }

        float s[4];
        #pragma unroll
        for (int i = 0; i < 4; i++) {
            __half2 h01 = __hmax2(__hadd2(*(__half2*)&u[i].x, *(__half2*)&m[i].x), z2);
            __half2 h23 = __hmax2(__hadd2(*(__half2*)&u[i].y, *(__half2*)&m[i].y), z2);
            float2 f01 = __half22float2(h01);
            float2 f23 = __half22float2(h23);
            float t = f01.x * wv.x;
            t = fmaf(f01.y, wv.y, t);
            t = fmaf(f23.x, wv.z, t);
            t = fmaf(f23.y, wv.w, t);
            s[i] = t;
        }

        #pragma unroll
        for (int i = 0; i < 4; i++)
            s[i] += __shfl_xor_sync(0xffffffffu, s[i], 16);
        float tA = hi_half ? s[1] : s[0];
        float tB = hi_half ? s[3] : s[2];
        tA += __shfl_xor_sync(0xffffffffu, tA, 8);
        tB += __shfl_xor_sync(0xffffffffu, tB, 8);
        tA += __shfl_xor_sync(0xffffffffu, tA, 4);
        tB += __shfl_xor_sync(0xffffffffu, tB, 4);
        tA += __shfl_xor_sync(0xffffffffu, tA, 2);
        tB += __shfl_xor_sync(0xffffffffu, tB, 2);
        tA += __shfl_xor_sync(0xffffffffu, tA, 1);
        tB += __shfl_xor_sync(0xffffffffu, tB, 1);

        if (lane == 0) {
            out[e0] = tA + bb;
            if (e0 + 2 < E) out[e0 + 2] = tB + bb;
        }
        if (lane == 16) {
            if (e0 + 1 < E) out[e0 + 1] = tA + bb;
            if (e0 + 3 < E) out[e0 + 3] = tB + bb;
        }
    }
}

// ---------------------------------------------------------------------------
extern "C" void kernel_launch(void* const* d_in, const int* in_sizes, int n_in,
                              void* d_out, int out_size)
{
    const float* user_emb  = (const float*)d_in[0];
    const float* movie_emb = (const float*)d_in[1];
    const int*   ei32      = (const int*)d_in[2];
    const float* w1        = (const float*)d_in[3];
    const float* b1        = (const float*)d_in[4];
    const float* w2        = (const float*)d_in[5];
    const float* b2        = (const float*)d_in[6];
    float*       out       = (float*)d_out;

    int n_users  = in_sizes[0] / HIDDEN;
    int n_movies = in_sizes[1] / HIDDEN;
    if (n_users  > MAX_USERS)  n_users  = MAX_USERS;
    if (n_movies > MAX_MOVIES) n_movies = MAX_MOVIES;
    int E = out_size;                       // out is [E, 1]

    size_t smem_bytes = (size_t)SM_PRE_FLOATS * sizeof(float);   // 199168 B
    cudaFuncSetAttribute(precompute_mma,
                         cudaFuncAttributeMaxDynamicSharedMemorySize,
                         (int)smem_bytes);

    init_probe_kernel<<<1, 32>>>(ei32);
    reduce_max_kernel<<<1184, 256>>>(ei32, E);

    const int g_user = 148, g_movie = 148;
    precompute_mma<<<g_user + g_movie, 256, smem_bytes>>>(
        user_emb, movie_emb, w1, b1, n_users, n_movies, g_user);

    edge_kernel<<<2048, 256>>>(ei32, w2, b2, out, E, n_users, n_movies);
}

// round 17
// speedup vs baseline: 1.4306x; 1.1726x over previous
#include <cuda_runtime.h>
#include <cuda_fp16.h>
#include <cstdint>

// EdgeDecoder: out[e] = relu(concat(user[i], movie[j]) @ w1^T + b1) @ w2^T + b2
//   U[i] = user_emb[i]  @ w1[:, :128]^T + b1   (mma.sync fp16 3-term split)
//   M[j] = movie_emb[j] @ w1[:, 128:]^T
//   out[e] = relu(U[i]+M[j]) . w2 + b2

#define HIDDEN      128
#define MAX_USERS   100000
#define MAX_MOVIES  50000
#define A_STRIDE    132   // padded fp32 row stride for A tile in smem

__device__ __align__(16) __half g_U[(size_t)MAX_USERS  * HIDDEN];
__device__ __align__(16) __half g_M[(size_t)MAX_MOVIES * HIDDEN];
__device__ int g_idx_is_i64;   // 1 if edge index buffer is int64, 0 if int32
__device__ int g_max_user;     // max referenced user index (exact)
__device__ int g_max_movie;    // max referenced movie index (exact)

__device__ __forceinline__ uint32_t h2_u32(__half2 h) {
    return *(uint32_t*)&h;
}
// fp16 mma m16n8k16: D(4xf32) += A(4xu32 = 8 halves) * B(2xu32 = 4 halves)
__device__ __forceinline__ void mma16(float4& d,
                                      uint32_t a0, uint32_t a1, uint32_t a2, uint32_t a3,
                                      uint32_t b0, uint32_t b1) {
    asm volatile(
        "mma.sync.aligned.m16n8k16.row.col.f32.f16.f16.f32 "
        "{%0,%1,%2,%3},{%4,%5,%6,%7},{%8,%9},{%0,%1,%2,%3};"
        : "+f"(d.x), "+f"(d.y), "+f"(d.z), "+f"(d.w)
        : "r"(a0), "r"(a1), "r"(a2), "r"(a3), "r"(b0), "r"(b1));
}

// ---------------------------------------------------------------------------
// Init+probe: warp-parallel dtype probe + zero max accumulators.
// ---------------------------------------------------------------------------
__global__ void init_probe_kernel(const int* __restrict__ ei32)
{
    int lane = threadIdx.x & 31;
    int nz = 0;
    #pragma unroll
    for (int k = 0; k < 4; k++) {
        int w = 8 * lane + 2 * k + 1;     // odd words 1..255
        if (ei32[w] != 0) nz = 1;
    }
    unsigned b = __ballot_sync(0xffffffffu, nz);
    if (lane == 0) {
        g_idx_is_i64 = (b == 0);
        g_max_user   = 0;
        g_max_movie  = 0;
    }
}

// ---------------------------------------------------------------------------
// Exact max-index reduction over both index rows.
// ---------------------------------------------------------------------------
__global__ __launch_bounds__(256)
void reduce_max_kernel(const int* __restrict__ ei32, int E)
{
    __shared__ int s_u[8], s_m[8];
    const int mode64 = g_idx_is_i64;
    int tid  = blockIdx.x * blockDim.x + threadIdx.x;
    int nthr = gridDim.x * blockDim.x;

    int mu = 0, mm = 0;
    if (mode64) {
        const int2* p = (const int2*)ei32;
        for (int e = tid; e < E; e += nthr) {
            mu = max(mu, p[e].x);
            mm = max(mm, p[E + e].x);
        }
    } else {
        for (int e = tid; e < E; e += nthr) {
            mu = max(mu, ei32[e]);
            mm = max(mm, ei32[E + e]);
        }
    }
    #pragma unroll
    for (int o = 16; o > 0; o >>= 1) {
        mu = max(mu, __shfl_xor_sync(0xffffffffu, mu, o));
        mm = max(mm, __shfl_xor_sync(0xffffffffu, mm, o));
    }
    int warp = threadIdx.x >> 5, lane = threadIdx.x & 31;
    if (lane == 0) { s_u[warp] = mu; s_m[warp] = mm; }
    __syncthreads();
    if (threadIdx.x == 0) {
        int bu = s_u[0], bm = s_m[0];
        #pragma unroll
        for (int w = 1; w < 8; w++) { bu = max(bu, s_u[w]); bm = max(bm, s_m[w]); }
        atomicMax(&g_max_user, bu);
        atomicMax(&g_max_movie, bm);
    }
}

// ---------------------------------------------------------------------------
// Tensor-core precompute via mma.sync m16n8k16 fp16 with exact 3-term split:
//   D = Ahi*Bhi + Alo*Bhi + Ahi*Blo   (residual ~2^-22: fp16 products are
//   exact in the fp32 accumulator)
// B fragments prepacked: Bs[kk][nb][lane] = uint4{b0hi,b1hi,b0lo,b1lo}.
// A tile (128 rows fp32, stride 132); per-kk fragments cvt'd on the fly.
// Each warp computes a 16x128 output slice; epilogue adds bias, stores fp16.
// ---------------------------------------------------------------------------
#define SM_B_U4      (8 * 16 * 32)                 // 4096 uint4 = 65536 B
#define SM_PRE_BYTES (128 * A_STRIDE * 4 + SM_B_U4 * 16 + 512 + 128)

__global__ __launch_bounds__(256, 1)
void precompute_mma(const float* __restrict__ user_emb,
                    const float* __restrict__ movie_emb,
                    const float* __restrict__ w1,
                    const float* __restrict__ b1,
                    int n_users, int n_movies, int g_user)
{
    extern __shared__ float sm[];
    float* As = sm;                              // [128][A_STRIDE] fp32
    uint4* Bs = (uint4*)(sm + 128 * A_STRIDE);   // [8kk][16nb][32lane]
    float* bs = (float*)(Bs + SM_B_U4);          // [128] bias

    const float* emb;
    __half*      outT;
    int nrows, addBias, cta, ncta;
    if ((int)blockIdx.x < g_user) {
        emb = user_emb;  outT = g_U;
        nrows = min(n_users, g_max_user + 1);
        addBias = 1; cta = blockIdx.x; ncta = g_user;
    } else {
        emb = movie_emb; outT = g_M;
        nrows = min(n_movies, g_max_movie + 1);
        addBias = 0; cta = blockIdx.x - g_user; ncta = gridDim.x - g_user;
    }
    int koff = addBias ? 0 : HIDDEN;
    int tid = threadIdx.x;

    // Stage B fragments (hi+lo fp16) and bias.
    // m16n8k16 B frag (col-major k16 x n8): lane g=t>>2 holds n=g;
    //   b0 = {B[k0][n], B[k0+1][n]}, b1 = {B[k0+8][n], B[k0+9][n]}, k0=(t&3)*2
    // with B[k][n] = w1[n][koff + kk*16 + k].
    for (int idx = tid; idx < 8 * 16 * 32; idx += 256) {
        int t  = idx & 31;
        int nb = (idx >> 5) & 15;
        int kk = idx >> 9;
        int n  = nb * 8 + (t >> 2);
        int k0 = kk * 16 + (t & 3) * 2;
        const float* wr = w1 + n * (2 * HIDDEN) + koff;
        float w00 = wr[k0],     w01 = wr[k0 + 1];
        float w10 = wr[k0 + 8], w11 = wr[k0 + 9];
        __half2 h0 = __floats2half2_rn(w00, w01);
        __half2 h1 = __floats2half2_rn(w10, w11);
        float2 f0 = __half22float2(h0);
        float2 f1 = __half22float2(h1);
        __half2 l0 = __floats2half2_rn(w00 - f0.x, w01 - f0.y);
        __half2 l1 = __floats2half2_rn(w10 - f1.x, w11 - f1.y);
        Bs[idx] = make_uint4(h2_u32(h0), h2_u32(h1), h2_u32(l0), h2_u32(l1));
    }
    if (tid < 128) bs[tid] = addBias ? b1[tid] : 0.f;
    __syncthreads();

    int warp = tid >> 5, lane = tid & 31;
    int r = lane >> 2, q = lane & 3;
    int ntiles = (nrows + 127) >> 7;

    for (int tile = cta; tile < ntiles; tile += ncta) {
        int row0 = tile << 7;

        // stage A tile: 128 rows x 128 floats (coalesced float4)
        for (int i = tid; i < 128 * 32; i += 256) {
            int rr = i >> 5, c4 = i & 31;
            int grow = min(row0 + rr, nrows - 1);
            float4 v = ((const float4*)(emb + (size_t)grow * HIDDEN))[c4];
            *(float4*)(As + rr * A_STRIDE + c4 * 4) = v;
        }
        __syncthreads();

        const float* Aw = As + (warp * 16) * A_STRIDE;
        float4 acc[16];
        #pragma unroll
        for (int nb = 0; nb < 16; nb++) acc[nb] = make_float4(0.f, 0.f, 0.f, 0.f);

        #pragma unroll
        for (int kk = 0; kk < 8; kk++) {
            // A frag (row-major m16 x k16): rows r, r+8; cols kk*16 + q*2 (+1), +8
            int c = kk * 16 + q * 2;
            float2 af0 = *(const float2*)(Aw + r * A_STRIDE + c);
            float2 af1 = *(const float2*)(Aw + (r + 8) * A_STRIDE + c);
            float2 af2 = *(const float2*)(Aw + r * A_STRIDE + c + 8);
            float2 af3 = *(const float2*)(Aw + (r + 8) * A_STRIDE + c + 8);
            __half2 ah0 = __floats2half2_rn(af0.x, af0.y);
            __half2 ah1 = __floats2half2_rn(af1.x, af1.y);
            __half2 ah2 = __floats2half2_rn(af2.x, af2.y);
            __half2 ah3 = __floats2half2_rn(af3.x, af3.y);
            float2 g0 = __half22float2(ah0), g1 = __half22float2(ah1);
            float2 g2 = __half22float2(ah2), g3 = __half22float2(ah3);
            uint32_t al0 = h2_u32(__floats2half2_rn(af0.x - g0.x, af0.y - g0.y));
            uint32_t al1 = h2_u32(__floats2half2_rn(af1.x - g1.x, af1.y - g1.y));
            uint32_t al2 = h2_u32(__floats2half2_rn(af2.x - g2.x, af2.y - g2.y));
            uint32_t al3 = h2_u32(__floats2half2_rn(af3.x - g3.x, af3.y - g3.y));
            uint32_t uh0 = h2_u32(ah0), uh1 = h2_u32(ah1);
            uint32_t uh2 = h2_u32(ah2), uh3 = h2_u32(ah3);

            const uint4* Bk = Bs + kk * 512 + lane;
            #pragma unroll
            for (int nb = 0; nb < 16; nb++) {
                uint4 bp = Bk[nb * 32];
                mma16(acc[nb], uh0, uh1, uh2, uh3, bp.x, bp.y);   // Ahi*Bhi
                mma16(acc[nb], al0, al1, al2, al3, bp.x, bp.y);   // Alo*Bhi
                mma16(acc[nb], uh0, uh1, uh2, uh3, bp.z, bp.w);   // Ahi*Blo
            }
        }

        // Epilogue: D frag rows r, r+8; cols nb*8 + q*2 (+1). fp16 store.
        int grow0 = row0 + warp * 16 + r;
        int grow1 = grow0 + 8;
        bool v0 = grow0 < nrows, v1 = grow1 < nrows;
        #pragma unroll
        for (int nb = 0; nb < 16; nb++) {
            int c = nb * 8 + q * 2;
            float2 bb = *(float2*)(bs + c);
            __half2 p0 = __floats2half2_rn(acc[nb].x + bb.x, acc[nb].y + bb.y);
            __half2 p1 = __floats2half2_rn(acc[nb].z + bb.x, acc[nb].w + bb.y);
            if (v0) *(__half2*)(outT + (size_t)grow0 * HIDDEN + c) = p0;
            if (v1) *(__half2*)(outT + (size_t)grow1 * HIDDEN + c) = p1;
        }
        __syncthreads();   // all warps done reading As before next restage
    }
}

// ---------------------------------------------------------------------------
// Edge kernel (R14 measured-best, 57us): warp per row, 4 edges/iter,
// vectorized index loads, two fused-dual shfl reductions, grid 2048.
// ---------------------------------------------------------------------------
__global__ __launch_bounds__(256)
void edge_kernel(const int* __restrict__ ei32,
                 const float* __restrict__ w2,
                 const float* __restrict__ b2,
                 float* __restrict__ out, int E,
                 int n_users, int n_movies)
{
    int lane = threadIdx.x & 31;
    int warp = (int)((blockIdx.x * blockDim.x + threadIdx.x) >> 5);
    int nw   = (int)((gridDim.x * blockDim.x) >> 5);

    const int mode64 = g_idx_is_i64;
    const int step = mode64 ? 2 : 1;
    const int moff = E * step;
    const unsigned ucl = (unsigned)(n_users - 1);
    const unsigned mcl = (unsigned)(n_movies - 1);
    const bool vec_ok = mode64 ? ((E & 1) == 0) : ((E & 3) == 0);

    float4 wv = ((const float4*)w2)[lane];
    float  bb = b2[0];
    const uint2* U2 = (const uint2*)g_U;   // row stride = 32 uint2 (256B)
    const uint2* M2 = (const uint2*)g_M;
    const bool hi_half = (lane & 16) != 0;
    const __half2 z2 = __float2half2_rn(0.f);

    for (int e0 = warp * 4; e0 < E; e0 += nw * 4) {
        unsigned iu[4], im[4];
        bool full = (e0 + 3 < E);

        if (full && vec_ok) {
            if (!mode64) {
                uint4 ru = *(const uint4*)(ei32 + e0);
                uint4 rm = *(const uint4*)(ei32 + E + e0);
                iu[0] = ru.x; iu[1] = ru.y; iu[2] = ru.z; iu[3] = ru.w;
                im[0] = rm.x; im[1] = rm.y; im[2] = rm.z; im[3] = rm.w;
            } else {
                const uint4* pu = (const uint4*)(ei32 + 2 * e0);
                uint4 a = pu[0], b = pu[1];
                iu[0] = a.x; iu[1] = a.z; iu[2] = b.x; iu[3] = b.z;
                const uint4* pm = (const uint4*)(ei32 + 2 * E + 2 * e0);
                uint4 c = pm[0], d = pm[1];
                im[0] = c.x; im[1] = c.z; im[2] = d.x; im[3] = d.z;
            }
        } else {
            #pragma unroll
            for (int i = 0; i < 4; i++) {
                int ec = min(e0 + i, E - 1);
                iu[i] = (unsigned)ei32[ec * step];
                im[i] = (unsigned)ei32[moff + ec * step];
            }
        }
        #pragma unroll
        for (int i = 0; i < 4; i++) {
            iu[i] = umin(iu[i], ucl);
            im[i] = umin(im[i], mcl);
        }

        uint2 u[4], m[4];
        #pragma unroll
        for (int i = 0; i < 4; i++) {
            u[i] = U2[(size_t)iu[i] * 32 + lane];
            m[i] = M2[(size_t)im[i] * 32 + lane];
        }

        float s[4];
        #pragma unroll
        for (int i = 0; i < 4; i++) {
            __half2 h01 = __hmax2(__hadd2(*(__half2*)&u[i].x, *(__half2*)&m[i].x), z2);
            __half2 h23 = __hmax2(__hadd2(*(__half2*)&u[i].y, *(__half2*)&m[i].y), z2);
            float2 f01 = __half22float2(h01);
            float2 f23 = __half22float2(h23);
            float t = f01.x * wv.x;
            t = fmaf(f01.y, wv.y, t);
            t = fmaf(f23.x, wv.z, t);
            t = fmaf(f23.y, wv.w, t);
            s[i] = t;
        }

        #pragma unroll
        for (int i = 0; i < 4; i++)
            s[i] += __shfl_xor_sync(0xffffffffu, s[i], 16);
        float tA = hi_half ? s[1] : s[0];
        float tB = hi_half ? s[3] : s[2];
        tA += __shfl_xor_sync(0xffffffffu, tA, 8);
        tB += __shfl_xor_sync(0xffffffffu, tB, 8);
        tA += __shfl_xor_sync(0xffffffffu, tA, 4);
        tB += __shfl_xor_sync(0xffffffffu, tB, 4);
        tA += __shfl_xor_sync(0xffffffffu, tA, 2);
        tB += __shfl_xor_sync(0xffffffffu, tB, 2);
        tA += __shfl_xor_sync(0xffffffffu, tA, 1);
        tB += __shfl_xor_sync(0xffffffffu, tB, 1);

        if (lane == 0) {
            out[e0] = tA + bb;
            if (e0 + 2 < E) out[e0 + 2] = tB + bb;
        }
        if (lane == 16) {
            if (e0 + 1 < E) out[e0 + 1] = tA + bb;
            if (e0 + 3 < E) out[e0 + 3] = tB + bb;
        }
    }
}

// ---------------------------------------------------------------------------
extern "C" void kernel_launch(void* const* d_in, const int* in_sizes, int n_in,
                              void* d_out, int out_size)
{
    const float* user_emb  = (const float*)d_in[0];
    const float* movie_emb = (const float*)d_in[1];
    const int*   ei32      = (const int*)d_in[2];
    const float* w1        = (const float*)d_in[3];
    const float* b1        = (const float*)d_in[4];
    const float* w2        = (const float*)d_in[5];
    const float* b2        = (const float*)d_in[6];
    float*       out       = (float*)d_out;

    int n_users  = in_sizes[0] / HIDDEN;
    int n_movies = in_sizes[1] / HIDDEN;
    if (n_users  > MAX_USERS)  n_users  = MAX_USERS;
    if (n_movies > MAX_MOVIES) n_movies = MAX_MOVIES;
    int E = out_size;                       // out is [E, 1]

    cudaFuncSetAttribute(precompute_mma,
                         cudaFuncAttributeMaxDynamicSharedMemorySize,
                         (int)SM_PRE_BYTES);   // ~134 KB

    init_probe_kernel<<<1, 32>>>(ei32);
    reduce_max_kernel<<<1184, 256>>>(ei32, E);

    const int g_user = 148, g_movie = 148;
    precompute_mma<<<g_user + g_movie, 256, SM_PRE_BYTES>>>(
        user_emb, movie_emb, w1, b1, n_users, n_movies, g_user);

    edge_kernel<<<2048, 256>>>(ei32, w2, b2, out, E, n_users, n_movies);
}